// round 7
// baseline (speedup 1.0000x reference)
#include <cuda_runtime.h>
#include <math.h>

#define N_NODES 100000
#define N_EDGES 1600000
#define IN_DIM  128
#define HID_DIM 256
#define OUT_DIM 128

// ---------------- scratch (device globals; no allocation allowed) ----------
__device__ int   g_is64;                               // edge_index dtype flag
__device__ int   g_deg[N_NODES];                       // degree / scatter cursor
__device__ int   g_rowptr[N_NODES + 1];                // CSR row pointers (by dst)
__device__ float g_dinv[N_NODES];                      // deg^-1/2 (incl self loop)
__device__ int   g_col[N_EDGES];                       // CSR column (src) indices
__device__ __align__(16) float g_agg1[(size_t)N_NODES * IN_DIM];   // S @ x  [N,128]
__device__ __align__(16) float g_h1[(size_t)N_NODES * HID_DIM];    // relu   [N,256]
__device__ __align__(16) float g_z[(size_t)N_NODES * OUT_DIM];     // h1@W2  [N,128]

// ---------------- edge_index accessors (int32 data, or int64 viewed as i32) -
// int32 layout: src = e32[e], dst = e32[N_EDGES + e]
// int64 layout (little-endian, values < 2^31): low words at even i32 indices:
//   src = e32[2*e], dst = e32[2*(N_EDGES + e)]
__device__ __forceinline__ int edge_src(const int* e32, int e) {
    int v = g_is64 ? e32[2 * e] : e32[e];
    return min(max(v, 0), N_NODES - 1);
}
__device__ __forceinline__ int edge_dst(const int* e32, int e) {
    int v = g_is64 ? e32[2 * (N_EDGES + e)] : e32[N_EDGES + e];
    return min(max(v, 0), N_NODES - 1);
}

// Probe: if data is int64 with values < 2^31, odd int32 words are all zero.
__global__ void k_detect(const int* e32) {
    if (threadIdx.x == 0 && blockIdx.x == 0) {
        int zeros = 0;
        for (int k = 0; k < 1024; k++) zeros += (e32[2 * k + 1] == 0) ? 1 : 0;
        g_is64 = (zeros > 512) ? 1 : 0;
    }
}

// ---------------- graph preprocessing --------------------------------------
__global__ void k_zero_deg() {
    int i = blockIdx.x * blockDim.x + threadIdx.x;
    if (i < N_NODES) g_deg[i] = 0;
}

__global__ void k_count(const int* e32) {
    int e = blockIdx.x * blockDim.x + threadIdx.x;
    if (e < N_EDGES) {
        int d = edge_dst(e32, e);
        atomicAdd(&g_deg[d], 1);
    }
}

__global__ void k_dinv() {
    int i = blockIdx.x * blockDim.x + threadIdx.x;
    if (i < N_NODES) g_dinv[i] = rsqrtf((float)(g_deg[i] + 1)); // +1 self loop
}

// single-block exclusive scan of g_deg -> g_rowptr (100001 entries)
__global__ void k_scan() {
    __shared__ int sums[1024];
    const int n = N_NODES;
    int t = threadIdx.x;
    const int chunk = (n + 1023) / 1024;
    int beg = t * chunk;
    int end = min(beg + chunk, n);
    if (beg > end) beg = end;
    int s = 0;
    for (int i = beg; i < end; i++) s += g_deg[i];
    sums[t] = s;
    __syncthreads();
    for (int off = 1; off < 1024; off <<= 1) {
        int v = (t >= off) ? sums[t - off] : 0;
        __syncthreads();
        sums[t] += v;
        __syncthreads();
    }
    int run = (t == 0) ? 0 : sums[t - 1];
    for (int i = beg; i < end; i++) { g_rowptr[i] = run; run += g_deg[i]; }
    if (t == 1023) g_rowptr[n] = sums[1023];
}

__global__ void k_scatter(const int* e32) {
    int e = blockIdx.x * blockDim.x + threadIdx.x;
    if (e < N_EDGES) {
        int s = edge_src(e32, e);
        int d = edge_dst(e32, e);
        int p = atomicAdd(&g_deg[d], 1);          // g_deg re-zeroed as cursor
        g_col[g_rowptr[d] + p] = s;
    }
}

// ---------------- aggregation (128 features, warp-per-node, float4) --------
// out[i,:] = sum_s dinv[s]*dinv[i] * xin[s,:]  + dinv[i]^2 * xin[i,:]  (+bias)
// 256 threads/block = 8 warps = 8 nodes per block. Lane handles 4 features.
__device__ __forceinline__ void agg_body(const float* xin, float* out,
                                         const float* bias) {
    int warp = threadIdx.x >> 5;
    int lane = threadIdx.x & 31;
    int i = blockIdx.x * 8 + warp;
    if (i >= N_NODES) return;

    const float4* xi = (const float4*)xin;
    float di = g_dinv[i];
    float4 xv = xi[(size_t)i * 32 + lane];
    float w = di * di;                       // self loop norm
    float4 acc;
    acc.x = w * xv.x; acc.y = w * xv.y; acc.z = w * xv.z; acc.w = w * xv.w;

    int j   = g_rowptr[i];
    int end = g_rowptr[i + 1];
    for (; j + 1 < end; j += 2) {
        int s0 = g_col[j];
        int s1 = g_col[j + 1];
        float w0 = g_dinv[s0] * di;
        float w1 = g_dinv[s1] * di;
        float4 v0 = xi[(size_t)s0 * 32 + lane];
        float4 v1 = xi[(size_t)s1 * 32 + lane];
        acc.x += w0 * v0.x + w1 * v1.x;
        acc.y += w0 * v0.y + w1 * v1.y;
        acc.z += w0 * v0.z + w1 * v1.z;
        acc.w += w0 * v0.w + w1 * v1.w;
    }
    if (j < end) {
        int s0 = g_col[j];
        float w0 = g_dinv[s0] * di;
        float4 v0 = xi[(size_t)s0 * 32 + lane];
        acc.x += w0 * v0.x;
        acc.y += w0 * v0.y;
        acc.z += w0 * v0.z;
        acc.w += w0 * v0.w;
    }
    if (bias) {
        acc.x += bias[lane * 4 + 0];
        acc.y += bias[lane * 4 + 1];
        acc.z += bias[lane * 4 + 2];
        acc.w += bias[lane * 4 + 3];
    }
    ((float4*)out)[(size_t)i * 32 + lane] = acc;
}

__global__ void k_agg_x(const float* x) {
    agg_body(x, g_agg1, (const float*)0);
}

__global__ void k_agg_out(const float* b2, float* out) {
    agg_body(g_z, out, b2);
}

// ---------------- SGEMM: C = A[M,K] @ B[K,N] -------------------------------
// 128x128 block tile, BK=8, 256 threads, 8x8 per-thread microtile.
#define BM 128
#define BN 128
#define BKK 8
#define TM 8
#define TN 8

// layer 1: g_agg1[N,128] @ W1[128,256] + b1, relu -> g_h1
__global__ __launch_bounds__(256, 2) void k_sgemm1(const float* B, const float* bias)
{
    __shared__ float As[BKK][BM];
    __shared__ float Bs[BKK][BN];
    const float* A = g_agg1;
    float* C = g_h1;
    const int M = N_NODES, N = HID_DIM, K = IN_DIM;

    int tid  = threadIdx.x;
    int row0 = blockIdx.y * BM;
    int col0 = blockIdx.x * BN;
    int a_r = tid >> 1;            // 0..127
    int a_c = (tid & 1) * 4;       // 0 or 4
    int a_row_g = row0 + a_r;
    if (a_row_g >= M) a_row_g = M - 1;   // clamp; results discarded in epilogue
    int b_r = tid >> 5;            // 0..7
    int b_c = (tid & 31) * 4;      // 0..124
    int ty = (tid >> 4) * TM;
    int tx = (tid & 15) * TN;

    float acc[TM][TN];
#pragma unroll
    for (int m = 0; m < TM; m++)
#pragma unroll
        for (int n = 0; n < TN; n++) acc[m][n] = 0.0f;

    for (int k0 = 0; k0 < K; k0 += BKK) {
        float4 av = *(const float4*)(A + (size_t)a_row_g * K + k0 + a_c);
        float4 bv = *(const float4*)(B + (size_t)(k0 + b_r) * N + col0 + b_c);
        As[a_c + 0][a_r] = av.x;
        As[a_c + 1][a_r] = av.y;
        As[a_c + 2][a_r] = av.z;
        As[a_c + 3][a_r] = av.w;
        *(float4*)&Bs[b_r][b_c] = bv;
        __syncthreads();
#pragma unroll
        for (int kk = 0; kk < BKK; kk++) {
            float a[TM], b[TN];
            *(float4*)&a[0] = *(const float4*)&As[kk][ty];
            *(float4*)&a[4] = *(const float4*)&As[kk][ty + 4];
            *(float4*)&b[0] = *(const float4*)&Bs[kk][tx];
            *(float4*)&b[4] = *(const float4*)&Bs[kk][tx + 4];
#pragma unroll
            for (int m = 0; m < TM; m++)
#pragma unroll
                for (int n = 0; n < TN; n++)
                    acc[m][n] = fmaf(a[m], b[n], acc[m][n]);
        }
        __syncthreads();
    }
#pragma unroll
    for (int m = 0; m < TM; m++) {
        int r = row0 + ty + m;
        if (r < M) {
#pragma unroll
            for (int n = 0; n < TN; n++) {
                int c = col0 + tx + n;
                float v = acc[m][n] + bias[c];
                C[(size_t)r * N + c] = fmaxf(v, 0.0f);   // relu
            }
        }
    }
}

// layer 2: g_h1[N,256] @ W2[256,128] -> g_z (no bias/relu here)
__global__ __launch_bounds__(256, 2) void k_sgemm2(const float* B)
{
    __shared__ float As[BKK][BM];
    __shared__ float Bs[BKK][BN];
    const float* A = g_h1;
    float* C = g_z;
    const int M = N_NODES, N = OUT_DIM, K = HID_DIM;

    int tid  = threadIdx.x;
    int row0 = blockIdx.y * BM;
    int col0 = blockIdx.x * BN;
    int a_r = tid >> 1;
    int a_c = (tid & 1) * 4;
    int a_row_g = row0 + a_r;
    if (a_row_g >= M) a_row_g = M - 1;
    int b_r = tid >> 5;
    int b_c = (tid & 31) * 4;
    int ty = (tid >> 4) * TM;
    int tx = (tid & 15) * TN;

    float acc[TM][TN];
#pragma unroll
    for (int m = 0; m < TM; m++)
#pragma unroll
        for (int n = 0; n < TN; n++) acc[m][n] = 0.0f;

    for (int k0 = 0; k0 < K; k0 += BKK) {
        float4 av = *(const float4*)(A + (size_t)a_row_g * K + k0 + a_c);
        float4 bv = *(const float4*)(B + (size_t)(k0 + b_r) * N + col0 + b_c);
        As[a_c + 0][a_r] = av.x;
        As[a_c + 1][a_r] = av.y;
        As[a_c + 2][a_r] = av.z;
        As[a_c + 3][a_r] = av.w;
        *(float4*)&Bs[b_r][b_c] = bv;
        __syncthreads();
#pragma unroll
        for (int kk = 0; kk < BKK; kk++) {
            float a[TM], b[TN];
            *(float4*)&a[0] = *(const float4*)&As[kk][ty];
            *(float4*)&a[4] = *(const float4*)&As[kk][ty + 4];
            *(float4*)&b[0] = *(const float4*)&Bs[kk][tx];
            *(float4*)&b[4] = *(const float4*)&Bs[kk][tx + 4];
#pragma unroll
            for (int m = 0; m < TM; m++)
#pragma unroll
                for (int n = 0; n < TN; n++)
                    acc[m][n] = fmaf(a[m], b[n], acc[m][n]);
        }
        __syncthreads();
    }
#pragma unroll
    for (int m = 0; m < TM; m++) {
        int r = row0 + ty + m;
        if (r < M) {
#pragma unroll
            for (int n = 0; n < TN; n++) {
                int c = col0 + tx + n;
                C[(size_t)r * N + c] = acc[m][n];
            }
        }
    }
}

// ---------------- launch ----------------------------------------------------
extern "C" void kernel_launch(void* const* d_in, const int* in_sizes, int n_in,
                              void* d_out, int out_size) {
    const float* x  = (const float*)d_in[0];
    const int*   ei = (const int*)d_in[1];      // int32 view of edge_index
    const float* W1 = (const float*)d_in[2];
    const float* b1 = (const float*)d_in[3];
    const float* W2 = (const float*)d_in[4];
    const float* b2 = (const float*)d_in[5];
    float* out = (float*)d_out;

    const int T = 256;
    int gn = (N_NODES + T - 1) / T;
    int ge = (N_EDGES + T - 1) / T;

    // dtype probe + CSR build (by dst) + normalization
    k_detect<<<1, 32>>>(ei);
    k_zero_deg<<<gn, T>>>();
    k_count<<<ge, T>>>(ei);
    k_dinv<<<gn, T>>>();
    k_scan<<<1, 1024>>>();
    k_zero_deg<<<gn, T>>>();
    k_scatter<<<ge, T>>>(ei);

    // layer 1: aggregate x (128) first, then transform 128->256 (+b1, relu)
    int gagg = (N_NODES + 7) / 8;
    k_agg_x<<<gagg, 256>>>(x);
    {
        dim3 grid(HID_DIM / BN, (N_NODES + BM - 1) / BM);
        k_sgemm1<<<grid, 256>>>(W1, b1);
    }

    // layer 2: transform 256->128 first, then aggregate (+b2)
    {
        dim3 grid(OUT_DIM / BN, (N_NODES + BM - 1) / BM);
        k_sgemm2<<<grid, 256>>>(W2);
    }
    k_agg_out<<<gagg, 256>>>(b2, out);
}

// round 8
// speedup vs baseline: 1.0886x; 1.0886x over previous
#include <cuda_runtime.h>
#include <math.h>

#define N_NODES 100000
#define N_EDGES 1600000
#define IN_DIM  128
#define HID_DIM 256
#define OUT_DIM 128

// ---------------- scratch (device globals; no allocation allowed) ----------
__device__ int   g_is64;                               // edge_index dtype flag
__device__ int   g_deg[N_NODES];                       // degree / scatter cursor
__device__ int   g_rowptr[N_NODES + 1];                // CSR row pointers (by dst)
__device__ float g_dinv[N_NODES];                      // deg^-1/2 (incl self loop)
__device__ int   g_col[N_EDGES];                       // CSR column (src) indices
__device__ __align__(16) float g_agg1[(size_t)N_NODES * IN_DIM];   // S @ x  [N,128]
__device__ __align__(16) float g_h1[(size_t)N_NODES * HID_DIM];    // relu   [N,256]
__device__ __align__(16) float g_z[(size_t)N_NODES * OUT_DIM];     // h1@W2  [N,128]

// packed fp32x2 FMA (Blackwell FFMA2; bit-exact 2x fp32 fma)
#define FMA_F32X2(acc, a, b) \
    asm("fma.rn.f32x2 %0, %1, %2, %0;" : "+l"(acc) : "l"(a), "l"(b))
#define DUP_F32X2(out, v) \
    asm("mov.b64 %0, {%1, %1};" : "=l"(out) : "f"(v))

// ---------------- edge_index accessors (int32 data, or int64 viewed as i32) -
__device__ __forceinline__ int edge_src(const int* e32, int e) {
    int v = g_is64 ? e32[2 * e] : e32[e];
    return min(max(v, 0), N_NODES - 1);
}
__device__ __forceinline__ int edge_dst(const int* e32, int e) {
    int v = g_is64 ? e32[2 * (N_EDGES + e)] : e32[N_EDGES + e];
    return min(max(v, 0), N_NODES - 1);
}

// Probe: if data is int64 with values < 2^31, odd int32 words are all zero.
__global__ void k_detect(const int* e32) {
    if (threadIdx.x == 0 && blockIdx.x == 0) {
        int zeros = 0;
        for (int k = 0; k < 1024; k++) zeros += (e32[2 * k + 1] == 0) ? 1 : 0;
        g_is64 = (zeros > 512) ? 1 : 0;
    }
}

// ---------------- graph preprocessing --------------------------------------
__global__ void k_zero_deg() {
    int i = blockIdx.x * blockDim.x + threadIdx.x;
    if (i < N_NODES) g_deg[i] = 0;
}

__global__ void k_count(const int* e32) {
    int e = blockIdx.x * blockDim.x + threadIdx.x;
    if (e < N_EDGES) {
        int d = edge_dst(e32, e);
        atomicAdd(&g_deg[d], 1);
    }
}

__global__ void k_dinv() {
    int i = blockIdx.x * blockDim.x + threadIdx.x;
    if (i < N_NODES) g_dinv[i] = rsqrtf((float)(g_deg[i] + 1)); // +1 self loop
}

// single-block exclusive scan of g_deg -> g_rowptr (100001 entries)
__global__ void k_scan() {
    __shared__ int sums[1024];
    const int n = N_NODES;
    int t = threadIdx.x;
    const int chunk = (n + 1023) / 1024;
    int beg = t * chunk;
    int end = min(beg + chunk, n);
    if (beg > end) beg = end;
    int s = 0;
    for (int i = beg; i < end; i++) s += g_deg[i];
    sums[t] = s;
    __syncthreads();
    for (int off = 1; off < 1024; off <<= 1) {
        int v = (t >= off) ? sums[t - off] : 0;
        __syncthreads();
        sums[t] += v;
        __syncthreads();
    }
    int run = (t == 0) ? 0 : sums[t - 1];
    for (int i = beg; i < end; i++) { g_rowptr[i] = run; run += g_deg[i]; }
    if (t == 1023) g_rowptr[n] = sums[1023];
}

__global__ void k_scatter(const int* e32) {
    int e = blockIdx.x * blockDim.x + threadIdx.x;
    if (e < N_EDGES) {
        int s = edge_src(e32, e);
        int d = edge_dst(e32, e);
        int p = atomicAdd(&g_deg[d], 1);          // g_deg re-zeroed as cursor
        g_col[g_rowptr[d] + p] = s;
    }
}

// ---------------- aggregation (128 features, warp-per-node, float4) --------
__device__ __forceinline__ void agg_body(const float* xin, float* out,
                                         const float* bias) {
    int warp = threadIdx.x >> 5;
    int lane = threadIdx.x & 31;
    int i = blockIdx.x * 8 + warp;
    if (i >= N_NODES) return;

    const float4* xi = (const float4*)xin;
    float di = g_dinv[i];
    float4 xv = xi[(size_t)i * 32 + lane];
    float w = di * di;                       // self loop norm
    float4 acc;
    acc.x = w * xv.x; acc.y = w * xv.y; acc.z = w * xv.z; acc.w = w * xv.w;

    int j   = g_rowptr[i];
    int end = g_rowptr[i + 1];
    for (; j + 1 < end; j += 2) {
        int s0 = g_col[j];
        int s1 = g_col[j + 1];
        float w0 = g_dinv[s0] * di;
        float w1 = g_dinv[s1] * di;
        float4 v0 = xi[(size_t)s0 * 32 + lane];
        float4 v1 = xi[(size_t)s1 * 32 + lane];
        acc.x += w0 * v0.x + w1 * v1.x;
        acc.y += w0 * v0.y + w1 * v1.y;
        acc.z += w0 * v0.z + w1 * v1.z;
        acc.w += w0 * v0.w + w1 * v1.w;
    }
    if (j < end) {
        int s0 = g_col[j];
        float w0 = g_dinv[s0] * di;
        float4 v0 = xi[(size_t)s0 * 32 + lane];
        acc.x += w0 * v0.x;
        acc.y += w0 * v0.y;
        acc.z += w0 * v0.z;
        acc.w += w0 * v0.w;
    }
    if (bias) {
        acc.x += bias[lane * 4 + 0];
        acc.y += bias[lane * 4 + 1];
        acc.z += bias[lane * 4 + 2];
        acc.w += bias[lane * 4 + 3];
    }
    ((float4*)out)[(size_t)i * 32 + lane] = acc;
}

__global__ void k_agg_x(const float* x) {
    agg_body(x, g_agg1, (const float*)0);
}

__global__ void k_agg_out(const float* b2, float* out) {
    agg_body(g_z, out, b2);
}

// ---------------- SGEMM: C = A[M,K] @ B[K,N] with packed f32x2 FMA ---------
// 128x128 block tile, BK=8, 256 threads, 8x8 per-thread microtile,
// accumulators held as 32 x f32x2 pairs (pairs along N).
#define BM 128
#define BN 128
#define BKK 8
#define TM 8
#define TN 8

// Shared GEMM body; A/C fixed pointers via template-ish duplication.
#define SGEMM_BODY(Aptr, Cptr, Mv, Nv, Kv, BIAS_RELU)                          \
    __shared__ float As[BKK][BM];                                              \
    __shared__ float Bs[BKK][BN];                                              \
    const float* A = (Aptr);                                                   \
    float* C = (Cptr);                                                         \
    const int M = (Mv), N = (Nv), K = (Kv);                                    \
    int tid  = threadIdx.x;                                                    \
    int row0 = blockIdx.y * BM;                                                \
    int col0 = blockIdx.x * BN;                                                \
    int a_r = tid >> 1;                                                        \
    int a_c = (tid & 1) * 4;                                                   \
    int a_row_g = row0 + a_r;                                                  \
    if (a_row_g >= M) a_row_g = M - 1;                                         \
    int b_r = tid >> 5;                                                        \
    int b_c = (tid & 31) * 4;                                                  \
    int ty = (tid >> 4) * TM;                                                  \
    int tx = (tid & 15) * TN;                                                  \
    unsigned long long acc2[TM][TN / 2];                                       \
    _Pragma("unroll")                                                          \
    for (int m = 0; m < TM; m++)                                               \
        _Pragma("unroll")                                                      \
        for (int p = 0; p < TN / 2; p++) acc2[m][p] = 0ULL;                    \
    for (int k0 = 0; k0 < K; k0 += BKK) {                                      \
        float4 av = *(const float4*)(A + (size_t)a_row_g * K + k0 + a_c);      \
        float4 bv = *(const float4*)(Bgl + (size_t)(k0 + b_r) * N + col0 + b_c);\
        As[a_c + 0][a_r] = av.x;                                               \
        As[a_c + 1][a_r] = av.y;                                               \
        As[a_c + 2][a_r] = av.z;                                               \
        As[a_c + 3][a_r] = av.w;                                               \
        *(float4*)&Bs[b_r][b_c] = bv;                                          \
        __syncthreads();                                                       \
        _Pragma("unroll")                                                      \
        for (int kk = 0; kk < BKK; kk++) {                                     \
            float a[TM];                                                       \
            *(float4*)&a[0] = *(const float4*)&As[kk][ty];                     \
            *(float4*)&a[4] = *(const float4*)&As[kk][ty + 4];                 \
            unsigned long long bd[TN / 2];                                     \
            *(float4*)&bd[0] = *(const float4*)&Bs[kk][tx];                    \
            *(float4*)&bd[2] = *(const float4*)&Bs[kk][tx + 4];                \
            unsigned long long ad[TM];                                         \
            _Pragma("unroll")                                                  \
            for (int m = 0; m < TM; m++) DUP_F32X2(ad[m], a[m]);               \
            _Pragma("unroll")                                                  \
            for (int m = 0; m < TM; m++)                                       \
                _Pragma("unroll")                                              \
                for (int p = 0; p < TN / 2; p++)                               \
                    FMA_F32X2(acc2[m][p], ad[m], bd[p]);                       \
        }                                                                      \
        __syncthreads();                                                       \
    }                                                                          \
    _Pragma("unroll")                                                          \
    for (int m = 0; m < TM; m++) {                                             \
        int r = row0 + ty + m;                                                 \
        if (r < M) {                                                           \
            _Pragma("unroll")                                                  \
            for (int p = 0; p < TN / 2; p++) {                                 \
                float2 f = *(float2*)&acc2[m][p];                              \
                int c = col0 + tx + 2 * p;                                     \
                BIAS_RELU(f.x, c);                                             \
                BIAS_RELU(f.y, (c + 1));                                       \
                C[(size_t)r * N + c]     = f.x;                                \
                C[(size_t)r * N + c + 1] = f.y;                                \
            }                                                                  \
        }                                                                      \
    }

#define EPI_RELU(v, c)  do { v = fmaxf(v + bias[c], 0.0f); } while (0)
#define EPI_NONE(v, c)  do { } while (0)

// layer 1: g_agg1[N,128] @ W1[128,256] + b1, relu -> g_h1
__global__ __launch_bounds__(256, 2) void k_sgemm1(const float* Bgl, const float* bias)
{
    SGEMM_BODY(g_agg1, g_h1, N_NODES, HID_DIM, IN_DIM, EPI_RELU)
}

// layer 2: g_h1[N,256] @ W2[256,128] -> g_z
__global__ __launch_bounds__(256, 2) void k_sgemm2(const float* Bgl)
{
    SGEMM_BODY(g_h1, g_z, N_NODES, OUT_DIM, HID_DIM, EPI_NONE)
}

// ---------------- launch ----------------------------------------------------
extern "C" void kernel_launch(void* const* d_in, const int* in_sizes, int n_in,
                              void* d_out, int out_size) {
    const float* x  = (const float*)d_in[0];
    const int*   ei = (const int*)d_in[1];      // int32 view of edge_index
    const float* W1 = (const float*)d_in[2];
    const float* b1 = (const float*)d_in[3];
    const float* W2 = (const float*)d_in[4];
    const float* b2 = (const float*)d_in[5];
    float* out = (float*)d_out;

    const int T = 256;
    int gn = (N_NODES + T - 1) / T;
    int ge = (N_EDGES + T - 1) / T;

    // dtype probe + CSR build (by dst) + normalization
    k_detect<<<1, 32>>>(ei);
    k_zero_deg<<<gn, T>>>();
    k_count<<<ge, T>>>(ei);
    k_dinv<<<gn, T>>>();
    k_scan<<<1, 1024>>>();
    k_zero_deg<<<gn, T>>>();
    k_scatter<<<ge, T>>>(ei);

    // layer 1: aggregate x (128) first, then transform 128->256 (+b1, relu)
    int gagg = (N_NODES + 7) / 8;
    k_agg_x<<<gagg, 256>>>(x);
    {
        dim3 grid(HID_DIM / BN, (N_NODES + BM - 1) / BM);
        k_sgemm1<<<grid, 256>>>(W1, b1);
    }

    // layer 2: transform 256->128 first, then aggregate (+b2)
    {
        dim3 grid(OUT_DIM / BN, (N_NODES + BM - 1) / BM);
        k_sgemm2<<<grid, 256>>>(W2);
    }
    k_agg_out<<<gagg, 256>>>(b2, out);
}

// round 11
// speedup vs baseline: 1.3782x; 1.2660x over previous
#include <cuda_runtime.h>
#include <cuda_bf16.h>
#include <math.h>
#include <stdint.h>

#define N_NODES 100000
#define N_EDGES 1600000
#define IN_DIM  128
#define HID_DIM 256
#define OUT_DIM 128

// ---------------- scratch (device globals; no allocation allowed) ----------
__device__ int   g_is64;
__device__ int   g_deg[N_NODES];
__device__ int   g_rowptr[N_NODES + 1];
__device__ float g_dinv[N_NODES];
__device__ int   g_col[N_EDGES];
__device__ __align__(16) float g_agg1[(size_t)N_NODES * IN_DIM];   // S @ x   [N,128]
__device__ __align__(16) float g_h1[(size_t)N_NODES * HID_DIM];    // relu    [N,256]
__device__ __align__(16) float g_z[(size_t)N_NODES * OUT_DIM];     // h1@W2   [N,128]
// weight images W^T: [N][K] k-major bf16, hi/lo split
__device__ __align__(16) unsigned short g_w1hi[256 * 128];
__device__ __align__(16) unsigned short g_w1lo[256 * 128];
__device__ __align__(16) unsigned short g_w2hi[128 * 256];
__device__ __align__(16) unsigned short g_w2lo[128 * 256];

// ---------------- warp-level bf16 MMA (base-target PTX, runs on HMMA) ------
#define MMA_BF16(c, a, b)                                                        \
    asm volatile("mma.sync.aligned.m16n8k16.row.col.f32.bf16.bf16.f32 "          \
        "{%0,%1,%2,%3}, {%4,%5,%6,%7}, {%8,%9}, {%0,%1,%2,%3};"                  \
        : "+f"((c)[0]), "+f"((c)[1]), "+f"((c)[2]), "+f"((c)[3])                 \
        : "r"((a)[0]), "r"((a)[1]), "r"((a)[2]), "r"((a)[3]),                    \
          "r"((b)[0]), "r"((b)[1]))

// ---------------- edge_index accessors --------------------------------------
__device__ __forceinline__ int edge_src(const int* e32, int e) {
    int v = g_is64 ? e32[2 * e] : e32[e];
    return min(max(v, 0), N_NODES - 1);
}
__device__ __forceinline__ int edge_dst(const int* e32, int e) {
    int v = g_is64 ? e32[2 * (N_EDGES + e)] : e32[N_EDGES + e];
    return min(max(v, 0), N_NODES - 1);
}

__global__ void k_detect(const int* e32) {
    if (threadIdx.x == 0 && blockIdx.x == 0) {
        int zeros = 0;
        for (int k = 0; k < 1024; k++) zeros += (e32[2 * k + 1] == 0) ? 1 : 0;
        g_is64 = (zeros > 512) ? 1 : 0;
    }
}

// ---------------- graph preprocessing --------------------------------------
__global__ void k_zero_deg() {
    int i = blockIdx.x * blockDim.x + threadIdx.x;
    if (i < N_NODES) g_deg[i] = 0;
}
__global__ void k_count(const int* e32) {
    int e = blockIdx.x * blockDim.x + threadIdx.x;
    if (e < N_EDGES) atomicAdd(&g_deg[edge_dst(e32, e)], 1);
}
__global__ void k_dinv() {
    int i = blockIdx.x * blockDim.x + threadIdx.x;
    if (i < N_NODES) g_dinv[i] = rsqrtf((float)(g_deg[i] + 1));
}
__global__ void k_scan() {
    __shared__ int sums[1024];
    const int n = N_NODES;
    int t = threadIdx.x;
    const int chunk = (n + 1023) / 1024;
    int beg = t * chunk;
    int end = min(beg + chunk, n);
    if (beg > end) beg = end;
    int s = 0;
    for (int i = beg; i < end; i++) s += g_deg[i];
    sums[t] = s;
    __syncthreads();
    for (int off = 1; off < 1024; off <<= 1) {
        int v = (t >= off) ? sums[t - off] : 0;
        __syncthreads();
        sums[t] += v;
        __syncthreads();
    }
    int run = (t == 0) ? 0 : sums[t - 1];
    for (int i = beg; i < end; i++) { g_rowptr[i] = run; run += g_deg[i]; }
    if (t == 1023) g_rowptr[n] = sums[1023];
}
__global__ void k_scatter(const int* e32) {
    int e = blockIdx.x * blockDim.x + threadIdx.x;
    if (e < N_EDGES) {
        int s = edge_src(e32, e);
        int d = edge_dst(e32, e);
        int p = atomicAdd(&g_deg[d], 1);
        g_col[g_rowptr[d] + p] = s;
    }
}

// ---------------- weight prep: transpose + bf16 hi/lo split -----------------
__global__ void k_prep_w1(const float* W1) {   // W1[128k,256n] -> g_w1*[n][k]
    int idx = blockIdx.x * blockDim.x + threadIdx.x;
    if (idx < 128 * 256) {
        int n = idx & 255, k = idx >> 8;
        float x = W1[k * 256 + n];
        __nv_bfloat16 h = __float2bfloat16(x);
        __nv_bfloat16 l = __float2bfloat16(x - __bfloat162float(h));
        g_w1hi[n * 128 + k] = *(unsigned short*)&h;
        g_w1lo[n * 128 + k] = *(unsigned short*)&l;
    }
}
__global__ void k_prep_w2(const float* W2) {   // W2[256k,128n] -> g_w2*[n][k]
    int idx = blockIdx.x * blockDim.x + threadIdx.x;
    if (idx < 256 * 128) {
        int n = idx & 127, k = idx >> 7;
        float x = W2[k * 128 + n];
        __nv_bfloat16 h = __float2bfloat16(x);
        __nv_bfloat16 l = __float2bfloat16(x - __bfloat162float(h));
        g_w2hi[n * 256 + k] = *(unsigned short*)&h;
        g_w2lo[n * 256 + k] = *(unsigned short*)&l;
    }
}

// ---------------- aggregation (128 features, warp-per-node, float4) --------
__device__ __forceinline__ void agg_body(const float* xin, float* out, const float* bias) {
    int warp = threadIdx.x >> 5;
    int lane = threadIdx.x & 31;
    int i = blockIdx.x * 8 + warp;
    if (i >= N_NODES) return;

    const float4* xi = (const float4*)xin;
    float di = g_dinv[i];
    float4 xv = xi[(size_t)i * 32 + lane];
    float w = di * di;
    float4 acc;
    acc.x = w * xv.x; acc.y = w * xv.y; acc.z = w * xv.z; acc.w = w * xv.w;

    int j = g_rowptr[i];
    int end = g_rowptr[i + 1];
    for (; j + 1 < end; j += 2) {
        int s0 = g_col[j];
        int s1 = g_col[j + 1];
        float w0 = g_dinv[s0] * di;
        float w1 = g_dinv[s1] * di;
        float4 v0 = xi[(size_t)s0 * 32 + lane];
        float4 v1 = xi[(size_t)s1 * 32 + lane];
        acc.x += w0 * v0.x + w1 * v1.x;
        acc.y += w0 * v0.y + w1 * v1.y;
        acc.z += w0 * v0.z + w1 * v1.z;
        acc.w += w0 * v0.w + w1 * v1.w;
    }
    if (j < end) {
        int s0 = g_col[j];
        float w0 = g_dinv[s0] * di;
        float4 v0 = xi[(size_t)s0 * 32 + lane];
        acc.x += w0 * v0.x; acc.y += w0 * v0.y; acc.z += w0 * v0.z; acc.w += w0 * v0.w;
    }
    if (bias) {
        acc.x += bias[lane * 4 + 0];
        acc.y += bias[lane * 4 + 1];
        acc.z += bias[lane * 4 + 2];
        acc.w += bias[lane * 4 + 3];
    }
    ((float4*)out)[(size_t)i * 32 + lane] = acc;
}

__global__ void k_agg_x(const float* x)               { agg_body(x,   g_agg1, (const float*)0); }
__global__ void k_agg_out(const float* b2, float* out){ agg_body(g_z, out,    b2); }

// ---------------- bf16 split GEMM via mma.sync ------------------------------
// C[128-row tile, 128-col tile] = A @ W^T, 3 passes (hi*hi + hi*lo + lo*hi).
// 512 threads = 16 warps (4x4), warp tile 32x32 (2 m-frags x 4 n-frags).
// Smem: A/B tiles as [128][136] bf16 (272B row stride -> conflict-free quads).
#define SMS 136                           // smem row stride in shorts
#define SM_BYTES (4 * 128 * SMS * 2)      // AHI, ALO, BHI, BLO

template <int LAYER>
__global__ __launch_bounds__(512, 1) void k_mma(const float* bias)
{
    constexpr int NBT  = (LAYER == 1) ? 256 : 128;   // C row stride
    constexpr int KTOT = (LAYER == 1) ? 128 : 256;
    constexpr int KH   = KTOT / 128;
    const float* A = (LAYER == 1) ? g_agg1 : g_h1;
    float*       C = (LAYER == 1) ? g_h1   : g_z;
    const unsigned short* WHI = (LAYER == 1) ? g_w1hi : g_w2hi;
    const unsigned short* WLO = (LAYER == 1) ? g_w1lo : g_w2lo;

    extern __shared__ __align__(16) unsigned short sm[];
    unsigned short* AHI = sm;
    unsigned short* ALO = sm + 128 * SMS;
    unsigned short* BHI = sm + 2 * 128 * SMS;
    unsigned short* BLO = sm + 3 * 128 * SMS;

    int tid  = threadIdx.x;
    int lane = tid & 31;
    int wid  = tid >> 5;
    int row0 = blockIdx.x * 128;
    int nc0  = blockIdx.y * 128;

    float c[2][4][4];
#pragma unroll
    for (int i = 0; i < 2; i++)
#pragma unroll
        for (int j = 0; j < 4; j++)
#pragma unroll
            for (int q = 0; q < 4; q++) c[i][j][q] = 0.0f;

    for (int h = 0; h < KH; h++) {
        // ---- load A chunk [128 rows x 128 k] fp32 -> bf16 hi/lo smem
        {
            int lr = tid >> 2;                 // 0..127
            int cb = (tid & 3) * 32;           // 0,32,64,96
            int gr = min(row0 + lr, N_NODES - 1);
            const float* arow = A + (size_t)gr * KTOT + h * 128 + cb;
#pragma unroll
            for (int c4 = 0; c4 < 32; c4 += 4) {
                float4 v = *(const float4*)(arow + c4);
                __nv_bfloat16 h0 = __float2bfloat16(v.x);
                __nv_bfloat16 h1 = __float2bfloat16(v.y);
                __nv_bfloat16 h2 = __float2bfloat16(v.z);
                __nv_bfloat16 h3 = __float2bfloat16(v.w);
                uint2 hp;
                hp.x = ((uint32_t)*(unsigned short*)&h1 << 16) | *(unsigned short*)&h0;
                hp.y = ((uint32_t)*(unsigned short*)&h3 << 16) | *(unsigned short*)&h2;
                *(uint2*)&AHI[lr * SMS + cb + c4] = hp;
                __nv_bfloat16 l0 = __float2bfloat16(v.x - __bfloat162float(h0));
                __nv_bfloat16 l1 = __float2bfloat16(v.y - __bfloat162float(h1));
                __nv_bfloat16 l2 = __float2bfloat16(v.z - __bfloat162float(h2));
                __nv_bfloat16 l3 = __float2bfloat16(v.w - __bfloat162float(h3));
                uint2 lp;
                lp.x = ((uint32_t)*(unsigned short*)&l1 << 16) | *(unsigned short*)&l0;
                lp.y = ((uint32_t)*(unsigned short*)&l3 << 16) | *(unsigned short*)&l2;
                *(uint2*)&ALO[lr * SMS + cb + c4] = lp;
            }
        }
        // ---- load B chunk [128 n x 128 k] bf16 images
        {
            int lr = tid >> 2;
            int cb = (tid & 3) * 32;
            const unsigned short* bh = WHI + (size_t)(nc0 + lr) * KTOT + h * 128 + cb;
            const unsigned short* bl = WLO + (size_t)(nc0 + lr) * KTOT + h * 128 + cb;
#pragma unroll
            for (int c8 = 0; c8 < 32; c8 += 8) {
                *(uint4*)&BHI[lr * SMS + cb + c8] = *(const uint4*)(bh + c8);
                *(uint4*)&BLO[lr * SMS + cb + c8] = *(const uint4*)(bl + c8);
            }
        }
        __syncthreads();

        // ---- mainloop
        int mr = (wid & 3) * 32 + (lane >> 2);     // A row for frag base
        int nr = (wid >> 2) * 32 + (lane >> 2);    // B row (n) for frag base
#pragma unroll
        for (int k0 = 0; k0 < 128; k0 += 16) {
            int kc = k0 + (lane & 3) * 2;
            uint32_t ah[2][4], al[2][4], bh[4][2], bl[4][2];
#pragma unroll
            for (int i = 0; i < 2; i++) {
                int base = (mr + 16 * i) * SMS + kc;
                ah[i][0] = *(const uint32_t*)&AHI[base];
                ah[i][1] = *(const uint32_t*)&AHI[base + 8 * SMS];
                ah[i][2] = *(const uint32_t*)&AHI[base + 8];
                ah[i][3] = *(const uint32_t*)&AHI[base + 8 * SMS + 8];
                al[i][0] = *(const uint32_t*)&ALO[base];
                al[i][1] = *(const uint32_t*)&ALO[base + 8 * SMS];
                al[i][2] = *(const uint32_t*)&ALO[base + 8];
                al[i][3] = *(const uint32_t*)&ALO[base + 8 * SMS + 8];
            }
#pragma unroll
            for (int j = 0; j < 4; j++) {
                int base = (nr + 8 * j) * SMS + kc;
                bh[j][0] = *(const uint32_t*)&BHI[base];
                bh[j][1] = *(const uint32_t*)&BHI[base + 8];
                bl[j][0] = *(const uint32_t*)&BLO[base];
                bl[j][1] = *(const uint32_t*)&BLO[base + 8];
            }
#pragma unroll
            for (int i = 0; i < 2; i++)
#pragma unroll
                for (int j = 0; j < 4; j++) {
                    MMA_BF16(c[i][j], ah[i], bh[j]);
                    MMA_BF16(c[i][j], ah[i], bl[j]);
                    MMA_BF16(c[i][j], al[i], bh[j]);
                }
        }
        __syncthreads();
    }

    // ---- epilogue
    int m0 = (wid & 3) * 32;
    int n0 = (wid >> 2) * 32;
#pragma unroll
    for (int i = 0; i < 2; i++) {
#pragma unroll
        for (int j = 0; j < 4; j++) {
            int row = row0 + m0 + 16 * i + (lane >> 2);
            int col = nc0 + n0 + 8 * j + (lane & 3) * 2;
            float2 v0 = make_float2(c[i][j][0], c[i][j][1]);
            float2 v1 = make_float2(c[i][j][2], c[i][j][3]);
            if (LAYER == 1) {
                float b0 = bias[col], b1 = bias[col + 1];
                v0.x = fmaxf(v0.x + b0, 0.0f);
                v0.y = fmaxf(v0.y + b1, 0.0f);
                v1.x = fmaxf(v1.x + b0, 0.0f);
                v1.y = fmaxf(v1.y + b1, 0.0f);
            }
            if (row < N_NODES)     *(float2*)(C + (size_t)row * NBT + col)       = v0;
            if (row + 8 < N_NODES) *(float2*)(C + (size_t)(row + 8) * NBT + col) = v1;
        }
    }
}

// ---------------- launch ----------------------------------------------------
extern "C" void kernel_launch(void* const* d_in, const int* in_sizes, int n_in,
                              void* d_out, int out_size) {
    const float* x  = (const float*)d_in[0];
    const int*   ei = (const int*)d_in[1];
    const float* W1 = (const float*)d_in[2];
    const float* b1 = (const float*)d_in[3];
    const float* W2 = (const float*)d_in[4];
    const float* b2 = (const float*)d_in[5];
    float* out = (float*)d_out;

    cudaFuncSetAttribute(k_mma<1>, cudaFuncAttributeMaxDynamicSharedMemorySize, SM_BYTES);
    cudaFuncSetAttribute(k_mma<2>, cudaFuncAttributeMaxDynamicSharedMemorySize, SM_BYTES);

    const int T = 256;
    int gn = (N_NODES + T - 1) / T;
    int ge = (N_EDGES + T - 1) / T;

    // dtype probe + CSR build + weight images
    k_detect<<<1, 32>>>(ei);
    k_zero_deg<<<gn, T>>>();
    k_count<<<ge, T>>>(ei);
    k_prep_w1<<<128, 256>>>(W1);
    k_prep_w2<<<128, 256>>>(W2);
    k_dinv<<<gn, T>>>();
    k_scan<<<1, 1024>>>();
    k_zero_deg<<<gn, T>>>();
    k_scatter<<<ge, T>>>(ei);

    // layer 1: aggregate (128 feats) then tensor transform 128->256 (+b1, relu)
    int gagg = (N_NODES + 7) / 8;
    int gtile = (N_NODES + 127) / 128;
    k_agg_x<<<gagg, 256>>>(x);
    {
        dim3 grid(gtile, HID_DIM / 128);
        k_mma<1><<<grid, 512, SM_BYTES>>>(b1);
    }

    // layer 2: tensor transform 256->128 then aggregate (+b2)
    {
        dim3 grid(gtile, OUT_DIM / 128);
        k_mma<2><<<grid, 512, SM_BYTES>>>(0);
    }
    k_agg_out<<<gagg, 256>>>(b2, out);
}

// round 12
// speedup vs baseline: 1.4907x; 1.0816x over previous
#include <cuda_runtime.h>
#include <cuda_bf16.h>
#include <math.h>
#include <stdint.h>

#define N_NODES 100000
#define N_EDGES 1600000
#define IN_DIM  128
#define HID_DIM 256
#define OUT_DIM 128

// ---------------- scratch (device globals; no allocation allowed) ----------
__device__ int   g_is64;
__device__ int   g_deg[N_NODES];
__device__ int   g_cur[N_NODES];                       // scatter cursor
__device__ int   g_rowptr[N_NODES + 1];
__device__ float g_dinv[N_NODES];
__device__ int   g_col[N_EDGES];
__device__ __align__(16) float g_agg1[(size_t)N_NODES * IN_DIM];   // S @ x   [N,128]
__device__ __align__(16) float g_h1[(size_t)N_NODES * HID_DIM];    // relu    [N,256]
__device__ __align__(16) float g_z[(size_t)N_NODES * OUT_DIM];     // h1@W2   [N,128]
// weight images W^T: [N][K] k-major bf16, hi/lo split
__device__ __align__(16) unsigned short g_w1hi[256 * 128];
__device__ __align__(16) unsigned short g_w1lo[256 * 128];
__device__ __align__(16) unsigned short g_w2hi[128 * 256];
__device__ __align__(16) unsigned short g_w2lo[128 * 256];

// ---------------- warp-level bf16 MMA (base-target PTX, runs on HMMA) ------
#define MMA_BF16(c, a, b)                                                        \
    asm volatile("mma.sync.aligned.m16n8k16.row.col.f32.bf16.bf16.f32 "          \
        "{%0,%1,%2,%3}, {%4,%5,%6,%7}, {%8,%9}, {%0,%1,%2,%3};"                  \
        : "+f"((c)[0]), "+f"((c)[1]), "+f"((c)[2]), "+f"((c)[3])                 \
        : "r"((a)[0]), "r"((a)[1]), "r"((a)[2]), "r"((a)[3]),                    \
          "r"((b)[0]), "r"((b)[1]))

// ---------------- edge_index accessors --------------------------------------
__device__ __forceinline__ int edge_src(const int* e32, int e) {
    int v = g_is64 ? e32[2 * e] : e32[e];
    return min(max(v, 0), N_NODES - 1);
}
__device__ __forceinline__ int edge_dst(const int* e32, int e) {
    int v = g_is64 ? e32[2 * (N_EDGES + e)] : e32[N_EDGES + e];
    return min(max(v, 0), N_NODES - 1);
}

// ---------------- init: zero deg/cursor + int64 dtype probe -----------------
__global__ void k_init(const int* e32) {
    int i = blockIdx.x * blockDim.x + threadIdx.x;
    if (i < N_NODES) { g_deg[i] = 0; g_cur[i] = 0; }
    if (i == 0) {
        int zeros = 0;
        for (int k = 0; k < 1024; k++) zeros += (e32[2 * k + 1] == 0) ? 1 : 0;
        g_is64 = (zeros > 512) ? 1 : 0;
    }
}

__global__ void k_count(const int* e32) {
    int e = blockIdx.x * blockDim.x + threadIdx.x;
    if (e < N_EDGES) atomicAdd(&g_deg[edge_dst(e32, e)], 1);
}

// exclusive scan of g_deg -> g_rowptr, with dinv fused into the first sweep
__global__ void k_scan() {
    __shared__ int sums[1024];
    const int n = N_NODES;
    int t = threadIdx.x;
    const int chunk = (n + 1023) / 1024;
    int beg = t * chunk;
    int end = min(beg + chunk, n);
    if (beg > end) beg = end;
    int s = 0;
    for (int i = beg; i < end; i++) {
        int d = g_deg[i];
        s += d;
        g_dinv[i] = rsqrtf((float)(d + 1));   // +1 self loop
    }
    sums[t] = s;
    __syncthreads();
    for (int off = 1; off < 1024; off <<= 1) {
        int v = (t >= off) ? sums[t - off] : 0;
        __syncthreads();
        sums[t] += v;
        __syncthreads();
    }
    int run = (t == 0) ? 0 : sums[t - 1];
    for (int i = beg; i < end; i++) { g_rowptr[i] = run; run += g_deg[i]; }
    if (t == 1023) g_rowptr[n] = sums[1023];
}

__global__ void k_scatter(const int* e32) {
    int e = blockIdx.x * blockDim.x + threadIdx.x;
    if (e < N_EDGES) {
        int s = edge_src(e32, e);
        int d = edge_dst(e32, e);
        int p = atomicAdd(&g_cur[d], 1);
        g_col[g_rowptr[d] + p] = s;
    }
}

// ---------------- weight prep: transpose + bf16 hi/lo split -----------------
__global__ void k_prep_w1(const float* W1) {   // W1[128k,256n] -> g_w1*[n][k]
    int idx = blockIdx.x * blockDim.x + threadIdx.x;
    if (idx < 128 * 256) {
        int n = idx & 255, k = idx >> 8;
        float x = W1[k * 256 + n];
        __nv_bfloat16 h = __float2bfloat16(x);
        __nv_bfloat16 l = __float2bfloat16(x - __bfloat162float(h));
        g_w1hi[n * 128 + k] = *(unsigned short*)&h;
        g_w1lo[n * 128 + k] = *(unsigned short*)&l;
    }
}
__global__ void k_prep_w2(const float* W2) {   // W2[256k,128n] -> g_w2*[n][k]
    int idx = blockIdx.x * blockDim.x + threadIdx.x;
    if (idx < 256 * 128) {
        int n = idx & 127, k = idx >> 7;
        float x = W2[k * 128 + n];
        __nv_bfloat16 h = __float2bfloat16(x);
        __nv_bfloat16 l = __float2bfloat16(x - __bfloat162float(h));
        g_w2hi[n * 256 + k] = *(unsigned short*)&h;
        g_w2lo[n * 256 + k] = *(unsigned short*)&l;
    }
}

// ---------------- aggregation (128 features, warp-per-node, float4, x4) ----
__device__ __forceinline__ void agg_body(const float* xin, float* out, const float* bias) {
    int warp = threadIdx.x >> 5;
    int lane = threadIdx.x & 31;
    int i = blockIdx.x * 8 + warp;
    if (i >= N_NODES) return;

    const float4* xi = (const float4*)xin;
    float di = g_dinv[i];
    float4 xv = xi[(size_t)i * 32 + lane];
    float w = di * di;
    float4 acc;
    acc.x = w * xv.x; acc.y = w * xv.y; acc.z = w * xv.z; acc.w = w * xv.w;

    int j = g_rowptr[i];
    int end = g_rowptr[i + 1];
    for (; j + 3 < end; j += 4) {
        int s0 = g_col[j];
        int s1 = g_col[j + 1];
        int s2 = g_col[j + 2];
        int s3 = g_col[j + 3];
        float w0 = g_dinv[s0] * di;
        float w1 = g_dinv[s1] * di;
        float w2 = g_dinv[s2] * di;
        float w3 = g_dinv[s3] * di;
        float4 v0 = xi[(size_t)s0 * 32 + lane];
        float4 v1 = xi[(size_t)s1 * 32 + lane];
        float4 v2 = xi[(size_t)s2 * 32 + lane];
        float4 v3 = xi[(size_t)s3 * 32 + lane];
        acc.x += (w0 * v0.x + w1 * v1.x) + (w2 * v2.x + w3 * v3.x);
        acc.y += (w0 * v0.y + w1 * v1.y) + (w2 * v2.y + w3 * v3.y);
        acc.z += (w0 * v0.z + w1 * v1.z) + (w2 * v2.z + w3 * v3.z);
        acc.w += (w0 * v0.w + w1 * v1.w) + (w2 * v2.w + w3 * v3.w);
    }
    for (; j < end; j++) {
        int s0 = g_col[j];
        float w0 = g_dinv[s0] * di;
        float4 v0 = xi[(size_t)s0 * 32 + lane];
        acc.x += w0 * v0.x; acc.y += w0 * v0.y; acc.z += w0 * v0.z; acc.w += w0 * v0.w;
    }
    if (bias) {
        acc.x += bias[lane * 4 + 0];
        acc.y += bias[lane * 4 + 1];
        acc.z += bias[lane * 4 + 2];
        acc.w += bias[lane * 4 + 3];
    }
    ((float4*)out)[(size_t)i * 32 + lane] = acc;
}

__global__ void k_agg_x(const float* x)               { agg_body(x,   g_agg1, (const float*)0); }
__global__ void k_agg_out(const float* b2, float* out){ agg_body(g_z, out,    b2); }

// ---------------- bf16 split GEMM via mma.sync, BK=64, 2 CTAs/SM ------------
// C[128-row, 128-col tile] = A @ W^T, 3 passes (hi*hi + hi*lo + lo*hi).
// 512 threads = 16 warps (4x4), warp tile 32x32. K chunked at 64.
// Smem: 4 tiles [128][72] bf16 = 73728 B -> 2 CTAs/SM for load/MMA overlap.
#define SMS 72                            // smem row stride in shorts (36w = 4 mod 32)
#define SM_BYTES (4 * 128 * SMS * 2)

template <int LAYER>
__global__ __launch_bounds__(512, 2) void k_mma(const float* bias)
{
    constexpr int NBT  = (LAYER == 1) ? 256 : 128;   // C row stride
    constexpr int KTOT = (LAYER == 1) ? 128 : 256;
    constexpr int KH   = KTOT / 64;
    const float* A = (LAYER == 1) ? g_agg1 : g_h1;
    float*       C = (LAYER == 1) ? g_h1   : g_z;
    const unsigned short* WHI = (LAYER == 1) ? g_w1hi : g_w2hi;
    const unsigned short* WLO = (LAYER == 1) ? g_w1lo : g_w2lo;

    extern __shared__ __align__(16) unsigned short sm[];
    unsigned short* AHI = sm;
    unsigned short* ALO = sm + 128 * SMS;
    unsigned short* BHI = sm + 2 * 128 * SMS;
    unsigned short* BLO = sm + 3 * 128 * SMS;

    int tid  = threadIdx.x;
    int lane = tid & 31;
    int wid  = tid >> 5;
    int row0 = blockIdx.x * 128;
    int nc0  = blockIdx.y * 128;

    float c[2][4][4];
#pragma unroll
    for (int i = 0; i < 2; i++)
#pragma unroll
        for (int j = 0; j < 4; j++)
#pragma unroll
            for (int q = 0; q < 4; q++) c[i][j][q] = 0.0f;

    for (int h = 0; h < KH; h++) {
        // ---- load A chunk [128 rows x 64 k] fp32 -> bf16 hi/lo smem
        {
            int lr = tid >> 2;                 // 0..127
            int cb = (tid & 3) * 16;           // 0,16,32,48
            int gr = min(row0 + lr, N_NODES - 1);
            const float* arow = A + (size_t)gr * KTOT + h * 64 + cb;
#pragma unroll
            for (int c4 = 0; c4 < 16; c4 += 4) {
                float4 v = *(const float4*)(arow + c4);
                __nv_bfloat16 h0 = __float2bfloat16(v.x);
                __nv_bfloat16 h1 = __float2bfloat16(v.y);
                __nv_bfloat16 h2 = __float2bfloat16(v.z);
                __nv_bfloat16 h3 = __float2bfloat16(v.w);
                uint2 hp;
                hp.x = ((uint32_t)*(unsigned short*)&h1 << 16) | *(unsigned short*)&h0;
                hp.y = ((uint32_t)*(unsigned short*)&h3 << 16) | *(unsigned short*)&h2;
                *(uint2*)&AHI[lr * SMS + cb + c4] = hp;
                __nv_bfloat16 l0 = __float2bfloat16(v.x - __bfloat162float(h0));
                __nv_bfloat16 l1 = __float2bfloat16(v.y - __bfloat162float(h1));
                __nv_bfloat16 l2 = __float2bfloat16(v.z - __bfloat162float(h2));
                __nv_bfloat16 l3 = __float2bfloat16(v.w - __bfloat162float(h3));
                uint2 lp;
                lp.x = ((uint32_t)*(unsigned short*)&l1 << 16) | *(unsigned short*)&l0;
                lp.y = ((uint32_t)*(unsigned short*)&l3 << 16) | *(unsigned short*)&l2;
                *(uint2*)&ALO[lr * SMS + cb + c4] = lp;
            }
        }
        // ---- load B chunk [128 n x 64 k] bf16 images
        {
            int lr = tid >> 2;
            int cb = (tid & 3) * 16;
            const unsigned short* bh = WHI + (size_t)(nc0 + lr) * KTOT + h * 64 + cb;
            const unsigned short* bl = WLO + (size_t)(nc0 + lr) * KTOT + h * 64 + cb;
#pragma unroll
            for (int c8 = 0; c8 < 16; c8 += 8) {
                *(uint4*)&BHI[lr * SMS + cb + c8] = *(const uint4*)(bh + c8);
                *(uint4*)&BLO[lr * SMS + cb + c8] = *(const uint4*)(bl + c8);
            }
        }
        __syncthreads();

        // ---- mainloop over this 64-k chunk
        int mr = (wid & 3) * 32 + (lane >> 2);
        int nr = (wid >> 2) * 32 + (lane >> 2);
#pragma unroll
        for (int k0 = 0; k0 < 64; k0 += 16) {
            int kc = k0 + (lane & 3) * 2;
            uint32_t ah[2][4], al[2][4], bh[4][2], bl[4][2];
#pragma unroll
            for (int i = 0; i < 2; i++) {
                int base = (mr + 16 * i) * SMS + kc;
                ah[i][0] = *(const uint32_t*)&AHI[base];
                ah[i][1] = *(const uint32_t*)&AHI[base + 8 * SMS];
                ah[i][2] = *(const uint32_t*)&AHI[base + 8];
                ah[i][3] = *(const uint32_t*)&AHI[base + 8 * SMS + 8];
                al[i][0] = *(const uint32_t*)&ALO[base];
                al[i][1] = *(const uint32_t*)&ALO[base + 8 * SMS];
                al[i][2] = *(const uint32_t*)&ALO[base + 8];
                al[i][3] = *(const uint32_t*)&ALO[base + 8 * SMS + 8];
            }
#pragma unroll
            for (int j = 0; j < 4; j++) {
                int base = (nr + 8 * j) * SMS + kc;
                bh[j][0] = *(const uint32_t*)&BHI[base];
                bh[j][1] = *(const uint32_t*)&BHI[base + 8];
                bl[j][0] = *(const uint32_t*)&BLO[base];
                bl[j][1] = *(const uint32_t*)&BLO[base + 8];
            }
#pragma unroll
            for (int i = 0; i < 2; i++)
#pragma unroll
                for (int j = 0; j < 4; j++) {
                    MMA_BF16(c[i][j], ah[i], bh[j]);
                    MMA_BF16(c[i][j], ah[i], bl[j]);
                    MMA_BF16(c[i][j], al[i], bh[j]);
                }
        }
        __syncthreads();
    }

    // ---- epilogue
    int m0 = (wid & 3) * 32;
    int n0 = (wid >> 2) * 32;
#pragma unroll
    for (int i = 0; i < 2; i++) {
#pragma unroll
        for (int j = 0; j < 4; j++) {
            int row = row0 + m0 + 16 * i + (lane >> 2);
            int col = nc0 + n0 + 8 * j + (lane & 3) * 2;
            float2 v0 = make_float2(c[i][j][0], c[i][j][1]);
            float2 v1 = make_float2(c[i][j][2], c[i][j][3]);
            if (LAYER == 1) {
                float b0 = bias[col], b1 = bias[col + 1];
                v0.x = fmaxf(v0.x + b0, 0.0f);
                v0.y = fmaxf(v0.y + b1, 0.0f);
                v1.x = fmaxf(v1.x + b0, 0.0f);
                v1.y = fmaxf(v1.y + b1, 0.0f);
            }
            if (row < N_NODES)     *(float2*)(C + (size_t)row * NBT + col)       = v0;
            if (row + 8 < N_NODES) *(float2*)(C + (size_t)(row + 8) * NBT + col) = v1;
        }
    }
}

// ---------------- launch ----------------------------------------------------
extern "C" void kernel_launch(void* const* d_in, const int* in_sizes, int n_in,
                              void* d_out, int out_size) {
    const float* x  = (const float*)d_in[0];
    const int*   ei = (const int*)d_in[1];
    const float* W1 = (const float*)d_in[2];
    const float* b1 = (const float*)d_in[3];
    const float* W2 = (const float*)d_in[4];
    const float* b2 = (const float*)d_in[5];
    float* out = (float*)d_out;

    cudaFuncSetAttribute(k_mma<1>, cudaFuncAttributeMaxDynamicSharedMemorySize, SM_BYTES);
    cudaFuncSetAttribute(k_mma<2>, cudaFuncAttributeMaxDynamicSharedMemorySize, SM_BYTES);

    const int T = 256;
    int gn = (N_NODES + T - 1) / T;
    int ge = (N_EDGES + T - 1) / T;

    // CSR build + weight images (10 launches total)
    k_init<<<gn, T>>>(ei);
    k_count<<<ge, T>>>(ei);
    k_prep_w1<<<128, 256>>>(W1);
    k_prep_w2<<<128, 256>>>(W2);
    k_scan<<<1, 1024>>>();
    k_scatter<<<ge, T>>>(ei);

    // layer 1: aggregate (128 feats) then tensor transform 128->256 (+b1, relu)
    int gagg = (N_NODES + 7) / 8;
    int gtile = (N_NODES + 127) / 128;
    k_agg_x<<<gagg, 256>>>(x);
    {
        dim3 grid(gtile, HID_DIM / 128);
        k_mma<1><<<grid, 512, SM_BYTES>>>(b1);
    }

    // layer 2: tensor transform 256->128 then aggregate (+b2)
    {
        dim3 grid(gtile, OUT_DIM / 128);
        k_mma<2><<<grid, 512, SM_BYTES>>>(0);
    }
    k_agg_out<<<gagg, 256>>>(b2, out);
}